// round 11
// baseline (speedup 1.0000x reference)
#include <cuda_runtime.h>

// ---------------------------------------------------------------------------
// Bayes_4294967296643 : full pipeline; conv via mma.sync tf32 (sm_100-safe)
// R11: R8's proven staging + 512-thread conv CTAs (4 warps/SMSP)
// ---------------------------------------------------------------------------

#define NB    4
#define CH    256
#define HW    4096
#define LPIX  16384
#define NCLS  20

typedef unsigned int u32;

// ---- scratch (device globals; no allocation allowed) ----------------------
__device__ float g_m[NB*HW];          // relu'd label heatmap (mask numerator)
__device__ float g_rmax[64];
__device__ float g_chansum[NB*CH];
__device__ float g_S[NB*CH];
__device__ float g_atti[4*25*LPIX];   // infusion attention  [a][k][p]
__device__ float g_attd[4*9*LPIX];    // diffusion attention [a][k][p]
__device__ float g_wsum[4*LPIX];
__device__ float g_wA[9*256*512];     // weights [tap][co][ci], tf32-rounded
__device__ float g_x[NB*512*HW];      // conv input, tf32-rounded

// cvt.rna.tf32.f32 needs a .b32 destination register
__device__ __forceinline__ float to_tf32(float x){
    u32 r; asm("cvt.rna.tf32.f32 %0, %1;" : "=r"(r) : "f"(x));
    return __uint_as_float(r);
}

// ---------------------------------------------------------------------------
// 0) fat prep kernel: blocks [0,4608) weight prep, blocks [4608,4672) mask
// ---------------------------------------------------------------------------
__global__ void k_prep(const float* __restrict__ conv_w,
                       const float* __restrict__ feats,
                       const float* __restrict__ wgap,
                       const int*   __restrict__ label){
    int bid = blockIdx.x;
    int t = threadIdx.x;
    if (bid < 4608){
        int idx = bid*256 + t;
        int ci = idx & 511;
        int r  = idx >> 9;
        int co = r & 255; int tap = r >> 8;
        int kh = tap/3, kw = tap - kh*3;
        g_wA[idx] = to_tf32(conv_w[(((size_t)co*512 + ci)*3 + kh)*3 + kw]);
        return;
    }
    int b2 = bid - 4608;
    int p = b2*256 + t;
    int n = p >> 12, hw = p & 4095;
    int lab = label[n];
    const float* f  = feats + (size_t)n*CH*HW + hw;
    const float* wg = wgap + lab*CH;
    float s = 0.f;
    #pragma unroll 8
    for (int c = 0; c < CH; c++) s = fmaf(f[(size_t)c*HW], wg[c], s);
    s = fmaxf(s, 0.f);
    g_m[p] = s;
    __shared__ float sm[256];
    sm[t] = s; __syncthreads();
    for (int st = 128; st; st >>= 1){
        if (t < st) sm[t] = fmaxf(sm[t], sm[t+st]);
        __syncthreads();
    }
    if (!t) g_rmax[b2] = sm[0];
}

// ---------------------------------------------------------------------------
// window attention, 4-way channel split
// ---------------------------------------------------------------------------
template<int KS, int DIL, bool MASKED>
__global__ void k_att4(const float* __restrict__ Wt, const float* __restrict__ Ct){
    constexpr int K2 = KS*KS;
    int tid = threadIdx.x, wid = tid >> 5, lane = tid & 31;
    int pl = lane & 7, csp = lane >> 3;
    int unit = blockIdx.x*64 + wid*8 + pl;
    int a = unit >> 14, p = unit & 16383;
    int n = p >> 12, hw = p & 4095, h = hw >> 6, w = hw & 63;

    __shared__ float ssc;
    if (MASKED){
        if (tid == 0){
            float s = g_rmax[n*16];
            #pragma unroll
            for (int j = 1; j < 16; j++) s = fmaxf(s, g_rmax[n*16 + j]);
            ssc = 1.f / fmaxf(s, 1.f);
        }
        __syncthreads();
    }

    int off[K2]; float acc[K2];
    #pragma unroll
    for (int fi = 0; fi < KS; fi++)
        #pragma unroll
        for (int fj = 0; fj < KS; fj++){
            int q  = fi*KS + fj;
            int hh = h + (fi - KS/2)*DIL, ww = w + (fj - KS/2)*DIL;
            off[q] = ((unsigned)hh < 64u && (unsigned)ww < 64u) ? hh*64 + ww : -1;
            acc[q] = 0.f;
        }
    const float* wb = Wt + (size_t)(n*CH + a*64 + csp*16)*HW;
    const float* cb = Ct + (size_t)(n*CH + a*64 + csp*16)*HW + hw;
    #pragma unroll 2
    for (int c = 0; c < 16; c++){
        float cv = cb[(size_t)c*HW];
        const float* wr = wb + (size_t)c*HW;
        #pragma unroll
        for (int q = 0; q < K2; q++)
            if (off[q] >= 0) acc[q] = fmaf(wr[off[q]], cv, acc[q]);
    }
    #pragma unroll
    for (int q = 0; q < K2; q++){
        acc[q] += __shfl_xor_sync(0xFFFFFFFFu, acc[q], 8);
        acc[q] += __shfl_xor_sync(0xFFFFFFFFu, acc[q], 16);
    }
    float mx = acc[0];
    #pragma unroll
    for (int q = 1; q < K2; q++) mx = fmaxf(mx, acc[q]);
    float ssum = 0.f;
    #pragma unroll
    for (int q = 0; q < K2; q++){ acc[q] = expf(acc[q]-mx); ssum += acc[q]; }
    float inv = 1.f / ssum;
    if (MASKED) inv *= g_m[p]*ssc;
    if (csp == 0){
        float* att = MASKED ? g_attd : g_atti;
        #pragma unroll
        for (int q = 0; q < K2; q++) att[(size_t)(a*K2+q)*LPIX + p] = acc[q]*inv;
    }
}

// scatter-weight sums for pred_r
__global__ void k_wsum(){
    int idx = blockIdx.x*256 + threadIdx.x;   // a*LPIX + p
    int a = idx >> 14, p = idx & 16383;
    int n = p >> 12, hw = p & 4095, h = hw >> 6, w = hw & 63;
    float s = 0.f;
    #pragma unroll
    for (int fi = 0; fi < 5; fi++)
        #pragma unroll
        for (int fj = 0; fj < 5; fj++){
            int q  = fi*5 + fj;
            int hh = h - (fi-2)*3, ww = w - (fj-2)*3;
            if ((unsigned)hh < 64u && (unsigned)ww < 64u)
                s += g_atti[(size_t)(a*25+q)*LPIX + (n<<12) + hh*64 + ww];
        }
    g_wsum[idx] = s;
}

// ---------------------------------------------------------------------------
// build conv input x = [feats*mask || feats_d], tf32-rounded
// ---------------------------------------------------------------------------
__global__ void k_build_x(const float* __restrict__ feats){
    int t = threadIdx.x;
    int p = blockIdx.x*256 + t;
    int n = p >> 12, hw = p & 4095, h = hw >> 6, w = hw & 63;
    __shared__ float ssc;
    if (t == 0){
        float s = g_rmax[n*16];
        #pragma unroll
        for (int j = 1; j < 16; j++) s = fmaxf(s, g_rmax[n*16 + j]);
        ssc = 1.f / fmaxf(s, 1.f);
    }
    __syncthreads();
    float mv = g_m[p]*ssc;
    const float* f  = feats + (size_t)n*CH*HW + hw;
    float*       x0 = g_x   + (size_t)n*512*HW + hw;
    int src[9];
    #pragma unroll
    for (int fi = 0; fi < 3; fi++)
        #pragma unroll
        for (int fj = 0; fj < 3; fj++){
            int q  = fi*3 + fj;
            int hh = h - (fi-1)*6, ww = w - (fj-1)*6;
            src[q] = ((unsigned)hh < 64u && (unsigned)ww < 64u) ? hh*64 + ww : -1;
        }
    #pragma unroll 4
    for (int c = 0; c < CH; c++) x0[(size_t)c*HW] = to_tf32(f[(size_t)c*HW]*mv);
    for (int a = 0; a < 4; a++){
        float av[9];
        #pragma unroll
        for (int q = 0; q < 9; q++)
            av[q] = (src[q] >= 0) ? g_attd[(size_t)(a*9+q)*LPIX + (n<<12) + src[q]] : 0.f;
        const float* fa = feats + (size_t)(n*CH + a*64)*HW;
        #pragma unroll 2
        for (int cc = 0; cc < 64; cc++){
            const float* fc = fa + (size_t)cc*HW;
            float s = 0.f;
            #pragma unroll
            for (int q = 0; q < 9; q++)
                if (src[q] >= 0) s = fmaf(fc[src[q]], av[q], s);
            x0[(size_t)(256 + a*64 + cc)*HW] = to_tf32(s);
        }
    }
}

// ---------------------------------------------------------------------------
// conv as implicit GEMM on mma.sync m16n8k8 tf32 — pair-packed smem
//   512 threads, 16 warps (4co x 4px), warp tile 32co x 32px (mi2 x ni4).
//   R8-style LDG->reg->STS staging (proven correct), single buffer, 2 syncs.
//   grid 256: blk = n*64 + cohalf*32 + ptile ; block tile 128co x 128px.
// ---------------------------------------------------------------------------
#define APAD 20
#define BPAD 132

__global__ void __launch_bounds__(512,1)
k_conv_mma(const float* __restrict__ bias, float* __restrict__ out){
    __shared__ float sA[128*APAD*2];   // 20.5 KB
    __shared__ float sB[16*BPAD*2];    // 16.9 KB
    int tid  = threadIdx.x;
    int wid  = tid >> 5, lane = tid & 31;
    int gid  = lane >> 2, tig = lane & 3;
    int wco  = wid & 3, wpx = wid >> 2;
    int blk  = blockIdx.x;
    int n    = blk >> 6;
    int cohalf = (blk >> 5) & 1;
    int p0   = (blk & 31) * 128;

    const float* xs = g_x + (size_t)n*512*HW;

    float acc[2][4][4];
    #pragma unroll
    for (int mi = 0; mi < 2; mi++)
        #pragma unroll
        for (int ni = 0; ni < 4; ni++)
            #pragma unroll
            for (int r = 0; r < 4; r++) acc[mi][ni][r] = 0.f;

    float ra[8], rb[8];
    // A: idx=e*512+tid -> co=idx>>5, ci=idx&31 ; B: ci=idx>>7, px=idx&127
    #define LOAD_CHUNK(I) { \
        int tap = (I) >> 4, ci0 = ((I) & 15) * 32; \
        int dh = tap/3 - 1, dw = tap - (tap/3)*3 - 1; \
        const float* wsrc = g_wA + ((size_t)(tap*256 + cohalf*128))*512 + ci0; \
        _Pragma("unroll") \
        for (int e = 0; e < 8; e++){ \
            int idx = e*512 + tid; \
            ra[e] = wsrc[(size_t)(idx>>5)*512 + (idx&31)]; \
            int ci = idx >> 7, pl = idx & 127; \
            int p = p0 + pl; \
            int hh = (p>>6) + dh, ww = (p&63) + dw; \
            rb[e] = ((unsigned)hh < 64u && (unsigned)ww < 64u) \
                  ? xs[(size_t)(ci0+ci)*HW + (hh<<6) + ww] : 0.f; \
        } }
    // pair-packed STS: pair = (ci>>3)*4 + (ci&3), comp = (ci>>2)&1
    #define STORE_CHUNK() { \
        _Pragma("unroll") \
        for (int e = 0; e < 8; e++){ \
            int idx = e*512 + tid; \
            int coA = idx>>5, ciA = idx&31; \
            sA[(coA*APAD + ((ciA>>3)*4 + (ciA&3)))*2 + ((ciA>>2)&1)] = ra[e]; \
            int ciB = idx>>7, pxB = idx&127; \
            sB[(((ciB>>3)*4 + (ciB&3))*BPAD + pxB)*2 + ((ciB>>2)&1)] = rb[e]; \
        } }

    LOAD_CHUNK(0);
    STORE_CHUNK();
    __syncthreads();

    int coA = wco*32 + gid;            // A fragment base row
    int pxB = wpx*32 + gid;            // B fragment base pixel

    for (int i = 0; i < 144; i++){
        if (i < 143) LOAD_CHUNK(i+1);

        #pragma unroll
        for (int ks = 0; ks < 4; ks++){
            int pr = ks*4 + tig;       // pair index for this k-step
            u32 af[2][4], bf[4][2];
            #pragma unroll
            for (int mi = 0; mi < 2; mi++){
                float2 va = *(const float2*)&sA[((coA + mi*16)*APAD + pr)*2];
                float2 vb = *(const float2*)&sA[((coA + mi*16 + 8)*APAD + pr)*2];
                af[mi][0] = __float_as_uint(va.x);
                af[mi][1] = __float_as_uint(vb.x);
                af[mi][2] = __float_as_uint(va.y);
                af[mi][3] = __float_as_uint(vb.y);
            }
            #pragma unroll
            for (int ni = 0; ni < 4; ni++){
                float2 v = *(const float2*)&sB[(pr*BPAD + pxB + ni*8)*2];
                bf[ni][0] = __float_as_uint(v.x);
                bf[ni][1] = __float_as_uint(v.y);
            }
            #pragma unroll
            for (int mi = 0; mi < 2; mi++)
                #pragma unroll
                for (int ni = 0; ni < 4; ni++){
                    float* d = acc[mi][ni];
                    asm volatile(
                        "mma.sync.aligned.m16n8k8.row.col.f32.tf32.tf32.f32 "
                        "{%0,%1,%2,%3}, {%4,%5,%6,%7}, {%8,%9}, {%0,%1,%2,%3};"
                        : "+f"(d[0]), "+f"(d[1]), "+f"(d[2]), "+f"(d[3])
                        : "r"(af[mi][0]), "r"(af[mi][1]), "r"(af[mi][2]),
                          "r"(af[mi][3]), "r"(bf[ni][0]), "r"(bf[ni][1]));
                }
        }
        __syncthreads();
        if (i < 143){
            STORE_CHUNK();
            __syncthreads();
        }
    }

    // epilogue: acc[mi][ni] row0=co, row1=co+8 ; cols 2*tig, 2*tig+1
    #pragma unroll
    for (int mi = 0; mi < 2; mi++){
        int co = cohalf*128 + wco*32 + mi*16 + gid;
        float bv0 = bias[co], bv8 = bias[co+8];
        float* o0 = out + ((size_t)(n*CH + co))*HW + p0;
        #pragma unroll
        for (int ni = 0; ni < 4; ni++){
            int px = wpx*32 + ni*8 + 2*tig;
            float2 v0 = { acc[mi][ni][0] + bv0, acc[mi][ni][1] + bv0 };
            float2 v1 = { acc[mi][ni][2] + bv8, acc[mi][ni][3] + bv8 };
            *(float2*)(o0 + px)        = v0;
            *(float2*)(o0 + 8*HW + px) = v1;
        }
    }
}

// ---------------------------------------------------------------------------
// fat sums kernel: blocks [0,1024) chansum, [1024,2048) wchansum
// ---------------------------------------------------------------------------
__global__ void k_sums(const float* __restrict__ feats){
    int bid = blockIdx.x;
    __shared__ float sm[256];
    if (bid < 1024){
        int nc = bid;
        const float4* f = (const float4*)(feats + (size_t)nc*HW);
        float s = 0.f;
        for (int i = threadIdx.x; i < HW/4; i += 256){
            float4 v = f[i]; s += (v.x+v.y)+(v.z+v.w);
        }
        sm[threadIdx.x] = s; __syncthreads();
        for (int st = 128; st; st >>= 1){
            if (threadIdx.x < st) sm[threadIdx.x] += sm[threadIdx.x+st];
            __syncthreads();
        }
        if (!threadIdx.x) g_chansum[nc] = sm[0];
    } else {
        int nc = bid - 1024;
        int n = nc >> 8, c = nc & 255, a = c >> 6;
        const float4* f  = (const float4*)(feats + (size_t)nc*HW);
        const float4* ws = (const float4*)(g_wsum + a*LPIX + n*HW);
        float s = 0.f;
        for (int i = threadIdx.x; i < HW/4; i += 256){
            float4 v = f[i], u = ws[i];
            s = fmaf(v.x,u.x, fmaf(v.y,u.y, fmaf(v.z,u.z, fmaf(v.w,u.w, s))));
        }
        sm[threadIdx.x] = s; __syncthreads();
        for (int st = 128; st; st >>= 1){
            if (threadIdx.x < st) sm[threadIdx.x] += sm[threadIdx.x+st];
            __syncthreads();
        }
        if (!threadIdx.x) g_S[nc] = sm[0];
    }
}

// both preds in one launch: block 0 -> pred, block 1 -> pred_r
__global__ void k_preds(const float* __restrict__ wg,
                        const float* __restrict__ wgr,
                        float* __restrict__ outp){
    int t = threadIdx.x;
    if (t >= NB*NCLS) return;
    int n = t / NCLS, k = t % NCLS;
    bool rp = (blockIdx.x == 1);
    const float* cs = (rp ? g_S : g_chansum) + n*CH;
    const float* w  = (rp ? wgr : wg) + k*CH;
    float s = 0.f;
    for (int c = 0; c < CH; c++) s = fmaf(w[c], cs[c], s);
    outp[rp*80 + t] = s * (1.f/HW);
}

// ---------------------------------------------------------------------------
extern "C" void kernel_launch(void* const* d_in, const int* in_sizes, int n_in,
                              void* d_out, int out_size){
    const float* feats   = (const float*)d_in[0];
    const float* Kin     = (const float*)d_in[1];
    const float* Qin     = (const float*)d_in[2];
    const float* w_gap   = (const float*)d_in[3];
    const float* w_gap_r = (const float*)d_in[4];
    const float* conv_w  = (const float*)d_in[5];
    const float* conv_b  = (const float*)d_in[6];
    const int*   label   = (const int*)d_in[7];
    float* out = (float*)d_out;

    // ncu captures 0-based launch index 3 -> k_conv_mma
    k_prep<<<4672,256>>>(conv_w, feats, w_gap, label);   // 0: wprep + mask
    k_att4<3,6,true><<<1024,256>>>(Kin, Qin);            // 1: diffusion att
    k_build_x<<<64,256>>>(feats);                        // 2
    k_conv_mma<<<256,512>>>(conv_b, out);                // 3  <-- profiled

    k_att4<5,3,false><<<1024,256>>>(Qin, Kin);           // 4: infusion att
    k_wsum<<<256,256>>>();                               // 5
    k_sums<<<2048,256>>>(feats);                         // 6: chansum+wchansum
    k_preds<<<2,128>>>(w_gap, w_gap_r, out + 4194304);   // 7
}

// round 15
// speedup vs baseline: 1.1098x; 1.1098x over previous
#include <cuda_runtime.h>

// ---------------------------------------------------------------------------
// Bayes_4294967296643 : full pipeline; conv via mma.sync tf32 (sm_100-safe)
// R15: R14 with the misaligned B-staging STS.128 reverted to float2 stores.
//      Single smem buffer (95.7KB), BP2=268, 64x64 warp tiles, halo-B reuse.
// ---------------------------------------------------------------------------

#define NB    4
#define CH    256
#define HW    4096
#define LPIX  16384
#define NCLS  20

typedef unsigned int u32;

// ---- scratch (device globals; no allocation allowed) ----------------------
__device__ float g_m[NB*HW];          // relu'd label heatmap (mask numerator)
__device__ float g_rmax[64];
__device__ float g_chansum[NB*CH];
__device__ float g_S[NB*CH];
__device__ float g_atti[4*25*LPIX];   // infusion attention  [a][k][p]
__device__ float g_attd[4*9*LPIX];    // diffusion attention [a][k][p]
__device__ float g_wsum[4*LPIX];
__device__ float g_wA[9*256*512];     // weights [tap][co][ci], tf32-rounded
__device__ float g_x[NB*512*HW];      // conv input, tf32-rounded

// cvt.rna.tf32.f32 needs a .b32 destination register
__device__ __forceinline__ float to_tf32(float x){
    u32 r; asm("cvt.rna.tf32.f32 %0, %1;" : "=r"(r) : "f"(x));
    return __uint_as_float(r);
}

// ---------------------------------------------------------------------------
// 0) fat prep kernel: blocks [0,4608) weight prep, blocks [4608,4672) mask
// ---------------------------------------------------------------------------
__global__ void k_prep(const float* __restrict__ conv_w,
                       const float* __restrict__ feats,
                       const float* __restrict__ wgap,
                       const int*   __restrict__ label){
    int bid = blockIdx.x;
    int t = threadIdx.x;
    if (bid < 4608){
        int idx = bid*256 + t;
        int ci = idx & 511;
        int r  = idx >> 9;
        int co = r & 255; int tap = r >> 8;
        int kh = tap/3, kw = tap - kh*3;
        g_wA[idx] = to_tf32(conv_w[(((size_t)co*512 + ci)*3 + kh)*3 + kw]);
        return;
    }
    int b2 = bid - 4608;
    int p = b2*256 + t;
    int n = p >> 12, hw = p & 4095;
    int lab = label[n];
    const float* f  = feats + (size_t)n*CH*HW + hw;
    const float* wg = wgap + lab*CH;
    float s = 0.f;
    #pragma unroll 8
    for (int c = 0; c < CH; c++) s = fmaf(f[(size_t)c*HW], wg[c], s);
    s = fmaxf(s, 0.f);
    g_m[p] = s;
    __shared__ float sm[256];
    sm[t] = s; __syncthreads();
    for (int st = 128; st; st >>= 1){
        if (t < st) sm[t] = fmaxf(sm[t], sm[t+st]);
        __syncthreads();
    }
    if (!t) g_rmax[b2] = sm[0];
}

// ---------------------------------------------------------------------------
// window attention, 4-way channel split
// ---------------------------------------------------------------------------
template<int KS, int DIL, bool MASKED>
__global__ void k_att4(const float* __restrict__ Wt, const float* __restrict__ Ct){
    constexpr int K2 = KS*KS;
    int tid = threadIdx.x, wid = tid >> 5, lane = tid & 31;
    int pl = lane & 7, csp = lane >> 3;
    int unit = blockIdx.x*64 + wid*8 + pl;
    int a = unit >> 14, p = unit & 16383;
    int n = p >> 12, hw = p & 4095, h = hw >> 6, w = hw & 63;

    __shared__ float ssc;
    if (MASKED){
        if (tid == 0){
            float s = g_rmax[n*16];
            #pragma unroll
            for (int j = 1; j < 16; j++) s = fmaxf(s, g_rmax[n*16 + j]);
            ssc = 1.f / fmaxf(s, 1.f);
        }
        __syncthreads();
    }

    int off[K2]; float acc[K2];
    #pragma unroll
    for (int fi = 0; fi < KS; fi++)
        #pragma unroll
        for (int fj = 0; fj < KS; fj++){
            int q  = fi*KS + fj;
            int hh = h + (fi - KS/2)*DIL, ww = w + (fj - KS/2)*DIL;
            off[q] = ((unsigned)hh < 64u && (unsigned)ww < 64u) ? hh*64 + ww : -1;
            acc[q] = 0.f;
        }
    const float* wb = Wt + (size_t)(n*CH + a*64 + csp*16)*HW;
    const float* cb = Ct + (size_t)(n*CH + a*64 + csp*16)*HW + hw;
    #pragma unroll 2
    for (int c = 0; c < 16; c++){
        float cv = cb[(size_t)c*HW];
        const float* wr = wb + (size_t)c*HW;
        #pragma unroll
        for (int q = 0; q < K2; q++)
            if (off[q] >= 0) acc[q] = fmaf(wr[off[q]], cv, acc[q]);
    }
    #pragma unroll
    for (int q = 0; q < K2; q++){
        acc[q] += __shfl_xor_sync(0xFFFFFFFFu, acc[q], 8);
        acc[q] += __shfl_xor_sync(0xFFFFFFFFu, acc[q], 16);
    }
    float mx = acc[0];
    #pragma unroll
    for (int q = 1; q < K2; q++) mx = fmaxf(mx, acc[q]);
    float ssum = 0.f;
    #pragma unroll
    for (int q = 0; q < K2; q++){ acc[q] = expf(acc[q]-mx); ssum += acc[q]; }
    float inv = 1.f / ssum;
    if (MASKED) inv *= g_m[p]*ssc;
    if (csp == 0){
        float* att = MASKED ? g_attd : g_atti;
        #pragma unroll
        for (int q = 0; q < K2; q++) att[(size_t)(a*K2+q)*LPIX + p] = acc[q]*inv;
    }
}

// scatter-weight sums for pred_r
__global__ void k_wsum(){
    int idx = blockIdx.x*256 + threadIdx.x;   // a*LPIX + p
    int a = idx >> 14, p = idx & 16383;
    int n = p >> 12, hw = p & 4095, h = hw >> 6, w = hw & 63;
    float s = 0.f;
    #pragma unroll
    for (int fi = 0; fi < 5; fi++)
        #pragma unroll
        for (int fj = 0; fj < 5; fj++){
            int q  = fi*5 + fj;
            int hh = h - (fi-2)*3, ww = w - (fj-2)*3;
            if ((unsigned)hh < 64u && (unsigned)ww < 64u)
                s += g_atti[(size_t)(a*25+q)*LPIX + (n<<12) + hh*64 + ww];
        }
    g_wsum[idx] = s;
}

// ---------------------------------------------------------------------------
// build conv input x = [feats*mask || feats_d], tf32-rounded
// ---------------------------------------------------------------------------
__global__ void k_build_x(const float* __restrict__ feats){
    int t = threadIdx.x;
    int p = blockIdx.x*256 + t;
    int n = p >> 12, hw = p & 4095, h = hw >> 6, w = hw & 63;
    __shared__ float ssc;
    if (t == 0){
        float s = g_rmax[n*16];
        #pragma unroll
        for (int j = 1; j < 16; j++) s = fmaxf(s, g_rmax[n*16 + j]);
        ssc = 1.f / fmaxf(s, 1.f);
    }
    __syncthreads();
    float mv = g_m[p]*ssc;
    const float* f  = feats + (size_t)n*CH*HW + hw;
    float*       x0 = g_x   + (size_t)n*512*HW + hw;
    int src[9];
    #pragma unroll
    for (int fi = 0; fi < 3; fi++)
        #pragma unroll
        for (int fj = 0; fj < 3; fj++){
            int q  = fi*3 + fj;
            int hh = h - (fi-1)*6, ww = w - (fj-1)*6;
            src[q] = ((unsigned)hh < 64u && (unsigned)ww < 64u) ? hh*64 + ww : -1;
        }
    #pragma unroll 4
    for (int c = 0; c < CH; c++) x0[(size_t)c*HW] = to_tf32(f[(size_t)c*HW]*mv);
    for (int a = 0; a < 4; a++){
        float av[9];
        #pragma unroll
        for (int q = 0; q < 9; q++)
            av[q] = (src[q] >= 0) ? g_attd[(size_t)(a*9+q)*LPIX + (n<<12) + src[q]] : 0.f;
        const float* fa = feats + (size_t)(n*CH + a*64)*HW;
        #pragma unroll 2
        for (int cc = 0; cc < 64; cc++){
            const float* fc = fa + (size_t)cc*HW;
            float s = 0.f;
            #pragma unroll
            for (int q = 0; q < 9; q++)
                if (src[q] >= 0) s = fmaf(fc[src[q]], av[q], s);
            x0[(size_t)(256 + a*64 + cc)*HW] = to_tf32(s);
        }
    }
}

// ---------------------------------------------------------------------------
// conv as implicit GEMM on mma.sync m16n8k8 tf32
//   256 thr / 8 warps (wco=wid&1 x wpx=wid>>1), warp tile 64co x 64px.
//   block tile 128co x 256px; grid 128 = 4n x 2cohalf x 16 px-tiles.
//   K loop: kh(3) x ci-chunk(16) x kw(3); B smem has w-halo (66 slots/row,
//   halos permanently zero) and is reused across the 3 kw taps.
//   SINGLE buffer; stage -> sync -> compute -> sync per chunk.
// Layouts:
//   A[kw3][co128][pair AP=20] float2 {W[co][ci], W[co][ci+4]},
//     pair = (ci>>3)*4 + (ci&3), comp = (ci>>2)&1.
//   B[pair16][slot BP2=268] float2 {X[ci][px'], X[ci+4][px']},
//     slot = hrow*66 + (w+1); slots w=-1,64 are zero halos.
//   NOTE: B staging must use float2 stores — slot base has odd parity
//   (the +1 halo shift), so float4 would be 8B-aligned only (trap).
// ---------------------------------------------------------------------------
#define AP   20
#define BP2  268
#define AFL  (3*128*AP*2)                 /* 15360 floats */
#define BFL  (16*BP2*2)                   /*  8576 floats */
#define BUFL (AFL + BFL)                  /* 23936 floats */
#define CONV_SMEM (BUFL*4)                /* 95744 bytes */

__global__ void __launch_bounds__(256,1)
k_conv_mma(const float* __restrict__ bias, float* __restrict__ out){
    extern __shared__ float dsm[];
    int tid  = threadIdx.x;
    int wid  = tid >> 5, lane = tid & 31;
    int gid  = lane >> 2, tig = lane & 3;
    int wco  = wid & 1, wpx = wid >> 1;
    int blk  = blockIdx.x;
    int n      = blk >> 5;
    int cohalf = (blk >> 4) & 1;
    int ptile  = blk & 15;
    int p0     = ptile * 256;
    int hbase  = ptile * 4;

    const float* xs = g_x + (size_t)n*512*HW;
    float* A2 = dsm;
    float* B2 = dsm + AFL;

    // zero the permanent B halo slots (128 of 256 threads, 1 each)
    if (tid < 128){
        int pr = tid >> 3, hrow = (tid >> 1) & 3, side = tid & 1;
        int slot = hrow*66 + side*65;
        B2[(pr*BP2 + slot)*2 + 0] = 0.f;
        B2[(pr*BP2 + slot)*2 + 1] = 0.f;
    }

    float acc[4][8][4];
    #pragma unroll
    for (int mi = 0; mi < 4; mi++)
        #pragma unroll
        for (int ni = 0; ni < 8; ni++)
            #pragma unroll
            for (int r = 0; r < 4; r++) acc[mi][ni][r] = 0.f;

    // staging constants
    int coS  = tid >> 1;               // A: co row (0..127)
    int half = tid & 1;                // A: ci half (0..1), ci_lo = half*16
    int gS   = tid >> 6;               // B: ci group (0..3)
    int sS   = tid & 63;
    int hrowS = sS >> 4;               // B: h row in tile (0..3)
    int w0S   = (sS & 15) * 4;         // B: w segment

    #define STAGE_CHUNK(C) { \
        int kh = (C) >> 4, cic = (C) & 15, ci0 = cic*32; \
        _Pragma("unroll") \
        for (int kw = 0; kw < 3; kw++){ \
            const float* srcA = g_wA \
                + ((size_t)((kh*3+kw)*256 + cohalf*128 + coS))*512 + ci0 + half*16; \
            float4 f0 = *(const float4*)(srcA + 0); \
            float4 f1 = *(const float4*)(srcA + 4); \
            float4 f2 = *(const float4*)(srcA + 8); \
            float4 f3 = *(const float4*)(srcA + 12); \
            float* dA = A2 + ((kw*128 + coS)*AP + half*8)*2; \
            *(float4*)(dA + 0)  = make_float4(f0.x, f1.x, f0.y, f1.y); \
            *(float4*)(dA + 4)  = make_float4(f0.z, f1.z, f0.w, f1.w); \
            *(float4*)(dA + 8)  = make_float4(f2.x, f3.x, f2.y, f3.y); \
            *(float4*)(dA + 12) = make_float4(f2.z, f3.z, f2.w, f3.w); \
        } \
        int r = hbase + hrowS + kh - 1; \
        bool val = (unsigned)r < 64u; \
        _Pragma("unroll") \
        for (int cpl = 0; cpl < 4; cpl++){ \
            int ci_a = ci0 + 8*gS + cpl; \
            float4 u = make_float4(0.f,0.f,0.f,0.f), v = u; \
            if (val){ \
                const float* s0 = xs + (size_t)ci_a*HW + r*64 + w0S; \
                u = *(const float4*)s0; \
                v = *(const float4*)(s0 + 4*HW); \
            } \
            float* dB = B2 + ((4*gS + cpl)*BP2 + hrowS*66 + 1 + w0S)*2; \
            *(float2*)(dB + 0) = make_float2(u.x, v.x); \
            *(float2*)(dB + 2) = make_float2(u.y, v.y); \
            *(float2*)(dB + 4) = make_float2(u.z, v.z); \
            *(float2*)(dB + 6) = make_float2(u.w, v.w); \
        } }

    int coA = wco*64 + gid;            // A fragment base row (within 128)
    int bBase = wpx*66 + 1 + gid;      // B fragment slot base (dw added later)

    for (int c = 0; c < 48; c++){
        STAGE_CHUNK(c);
        __syncthreads();

        #pragma unroll
        for (int kw = 0; kw < 3; kw++){
            const float* Ak = A2 + (kw*128)*AP*2;
            int bOff = bBase + (kw - 1);
            #pragma unroll
            for (int ks = 0; ks < 4; ks++){
                int pr = ks*4 + tig;
                u32 af[4][4], bf[8][2];
                #pragma unroll
                for (int mi = 0; mi < 4; mi++){
                    float2 va = *(const float2*)&Ak[((coA + mi*16)*AP + pr)*2];
                    float2 vb = *(const float2*)&Ak[((coA + mi*16 + 8)*AP + pr)*2];
                    af[mi][0] = __float_as_uint(va.x);
                    af[mi][1] = __float_as_uint(vb.x);
                    af[mi][2] = __float_as_uint(va.y);
                    af[mi][3] = __float_as_uint(vb.y);
                }
                #pragma unroll
                for (int ni = 0; ni < 8; ni++){
                    float2 v = *(const float2*)&B2[(pr*BP2 + bOff + ni*8)*2];
                    bf[ni][0] = __float_as_uint(v.x);
                    bf[ni][1] = __float_as_uint(v.y);
                }
                #pragma unroll
                for (int mi = 0; mi < 4; mi++)
                    #pragma unroll
                    for (int ni = 0; ni < 8; ni++){
                        float* d = acc[mi][ni];
                        asm volatile(
                            "mma.sync.aligned.m16n8k8.row.col.f32.tf32.tf32.f32 "
                            "{%0,%1,%2,%3}, {%4,%5,%6,%7}, {%8,%9}, {%0,%1,%2,%3};"
                            : "+f"(d[0]), "+f"(d[1]), "+f"(d[2]), "+f"(d[3])
                            : "r"(af[mi][0]), "r"(af[mi][1]), "r"(af[mi][2]),
                              "r"(af[mi][3]), "r"(bf[ni][0]), "r"(bf[ni][1]));
                    }
            }
        }
        __syncthreads();
    }

    // epilogue: acc[mi][ni] row0=co, row1=co+8 ; cols 2*tig, 2*tig+1
    #pragma unroll
    for (int mi = 0; mi < 4; mi++){
        int co = cohalf*128 + wco*64 + mi*16 + gid;
        float bv0 = bias[co], bv8 = bias[co+8];
        float* o0 = out + ((size_t)(n*CH + co))*HW + p0;
        #pragma unroll
        for (int ni = 0; ni < 8; ni++){
            int px = wpx*64 + ni*8 + 2*tig;
            float2 v0 = { acc[mi][ni][0] + bv0, acc[mi][ni][1] + bv0 };
            float2 v1 = { acc[mi][ni][2] + bv8, acc[mi][ni][3] + bv8 };
            *(float2*)(o0 + px)        = v0;
            *(float2*)(o0 + 8*HW + px) = v1;
        }
    }
}

// ---------------------------------------------------------------------------
// fat sums kernel: blocks [0,1024) chansum, [1024,2048) wchansum
// ---------------------------------------------------------------------------
__global__ void k_sums(const float* __restrict__ feats){
    int bid = blockIdx.x;
    __shared__ float sm[256];
    if (bid < 1024){
        int nc = bid;
        const float4* f = (const float4*)(feats + (size_t)nc*HW);
        float s = 0.f;
        for (int i = threadIdx.x; i < HW/4; i += 256){
            float4 v = f[i]; s += (v.x+v.y)+(v.z+v.w);
        }
        sm[threadIdx.x] = s; __syncthreads();
        for (int st = 128; st; st >>= 1){
            if (threadIdx.x < st) sm[threadIdx.x] += sm[threadIdx.x+st];
            __syncthreads();
        }
        if (!threadIdx.x) g_chansum[nc] = sm[0];
    } else {
        int nc = bid - 1024;
        int n = nc >> 8, c = nc & 255, a = c >> 6;
        const float4* f  = (const float4*)(feats + (size_t)nc*HW);
        const float4* ws = (const float4*)(g_wsum + a*LPIX + n*HW);
        float s = 0.f;
        for (int i = threadIdx.x; i < HW/4; i += 256){
            float4 v = f[i], u = ws[i];
            s = fmaf(v.x,u.x, fmaf(v.y,u.y, fmaf(v.z,u.z, fmaf(v.w,u.w, s))));
        }
        sm[threadIdx.x] = s; __syncthreads();
        for (int st = 128; st; st >>= 1){
            if (threadIdx.x < st) sm[threadIdx.x] += sm[threadIdx.x+st];
            __syncthreads();
        }
        if (!threadIdx.x) g_S[nc] = sm[0];
    }
}

// both preds in one launch: block 0 -> pred, block 1 -> pred_r
__global__ void k_preds(const float* __restrict__ wg,
                        const float* __restrict__ wgr,
                        float* __restrict__ outp){
    int t = threadIdx.x;
    if (t >= NB*NCLS) return;
    int n = t / NCLS, k = t % NCLS;
    bool rp = (blockIdx.x == 1);
    const float* cs = (rp ? g_S : g_chansum) + n*CH;
    const float* w  = (rp ? wgr : wg) + k*CH;
    float s = 0.f;
    for (int c = 0; c < CH; c++) s = fmaf(w[c], cs[c], s);
    outp[rp*80 + t] = s * (1.f/HW);
}

// ---------------------------------------------------------------------------
extern "C" void kernel_launch(void* const* d_in, const int* in_sizes, int n_in,
                              void* d_out, int out_size){
    const float* feats   = (const float*)d_in[0];
    const float* Kin     = (const float*)d_in[1];
    const float* Qin     = (const float*)d_in[2];
    const float* w_gap   = (const float*)d_in[3];
    const float* w_gap_r = (const float*)d_in[4];
    const float* conv_w  = (const float*)d_in[5];
    const float* conv_b  = (const float*)d_in[6];
    const int*   label   = (const int*)d_in[7];
    float* out = (float*)d_out;

    cudaFuncSetAttribute(k_conv_mma, cudaFuncAttributeMaxDynamicSharedMemorySize,
                         CONV_SMEM);

    // ncu captures 0-based launch index 3 -> k_conv_mma
    k_prep<<<4672,256>>>(conv_w, feats, w_gap, label);   // 0: wprep + mask
    k_att4<3,6,true><<<1024,256>>>(Kin, Qin);            // 1: diffusion att
    k_build_x<<<64,256>>>(feats);                        // 2
    k_conv_mma<<<128,256,CONV_SMEM>>>(conv_b, out);      // 3  <-- profiled

    k_att4<5,3,false><<<1024,256>>>(Qin, Kin);           // 4: infusion att
    k_wsum<<<256,256>>>();                               // 5
    k_sums<<<2048,256>>>(feats);                         // 6: chansum+wchansum
    k_preds<<<2,128>>>(w_gap, w_gap_r, out + 4194304);   // 7
}